// round 10
// baseline (speedup 1.0000x reference)
#include <cuda_runtime.h>

// ---- problem-size caps (ref: N=100000, E=1600000, G=512, F=128) ----
#define MAXN 131072
#define MAXE 2000000
#define NSM  148
#define SCAN_TB 1024
#define MAXBLK (MAXN / SCAN_TB)   // 128

// scratch (no cudaMalloc allowed)
__device__ float  g_dot[MAXN];       // x@W per node
__device__ int    g_cnt[MAXN];       // in-degree count (deg = cnt + 1)
__device__ int    g_bstart[MAXN + 1];// CSR rowptr (by col), exclusive scan of cnt
__device__ int    g_cur[MAXN];       // bump cursors (init = bstart)
__device__ float  g_dinv[MAXN];      // 1/deg
__device__ float  g_dis[MAXN];       // deg^-1/2
__device__ float2 g_buf[4][MAXN];    // hop buffers {t, s}; gather computes t*s
__device__ int    g_bsum[MAXBLK];    // scan block partials
__device__ int    g_row[MAXE];       // source rows, grouped by col

#if defined(__CUDA_ARCH__) && (__CUDA_ARCH__ >= 900)
#define GRID_DEP_SYNC() cudaGridDependencySynchronize()
#else
#define GRID_DEP_SYNC()
#endif

// ---------------------------------------------------------------------------
// Fused preamble: GEMV blocks + degree-count blocks
// ---------------------------------------------------------------------------
__global__ void k_pre(const float* __restrict__ x, const float* __restrict__ W,
                      const int* __restrict__ col,
                      int n, int F, int E, int nGemv) {
    int lane = threadIdx.x & 31;
    if (blockIdx.x < nGemv) {
        int warp   = (blockIdx.x * blockDim.x + threadIdx.x) >> 5;
        int nwarps = (nGemv * blockDim.x) >> 5;
        if (F == 128) {
            float4 wv = *reinterpret_cast<const float4*>(W + lane * 4);
            for (int node = warp; node < n; node += nwarps) {
                float4 xv = *reinterpret_cast<const float4*>(x + (size_t)node * 128 + lane * 4);
                float acc = xv.x * wv.x + xv.y * wv.y + xv.z * wv.z + xv.w * wv.w;
                #pragma unroll
                for (int o = 16; o; o >>= 1) acc += __shfl_xor_sync(0xffffffffu, acc, o);
                if (lane == 0) g_dot[node] = acc;
            }
        } else {
            for (int node = warp; node < n; node += nwarps) {
                const float* xr = x + (size_t)node * F;
                float acc = 0.0f;
                for (int j = lane; j < F; j += 32) acc += xr[j] * W[j];
                #pragma unroll
                for (int o = 16; o; o >>= 1) acc += __shfl_xor_sync(0xffffffffu, acc, o);
                if (lane == 0) g_dot[node] = acc;
            }
        }
    } else {
        int tid = (blockIdx.x - nGemv) * blockDim.x + threadIdx.x;
        int nth = (gridDim.x - nGemv) * blockDim.x;
        int E4  = E >> 2;
        for (int q = tid; q < E4; q += nth) {
            int4 c = reinterpret_cast<const int4*>(col)[q];
            atomicAdd(&g_cnt[c.x], 1);
            atomicAdd(&g_cnt[c.y], 1);
            atomicAdd(&g_cnt[c.z], 1);
            atomicAdd(&g_cnt[c.w], 1);
        }
        if (tid == 0) for (int e = E4 << 2; e < E; e++) atomicAdd(&g_cnt[col[e]], 1);
    }
}

// ---- scan phase A: per-block totals of g_cnt ----
__global__ void k_scanA(int n) {
    GRID_DEP_SYNC();
    int i = blockIdx.x * SCAN_TB + threadIdx.x;
    int lane = threadIdx.x & 31;
    int warp = threadIdx.x >> 5;
    int v = (i < n) ? g_cnt[i] : 0;
    #pragma unroll
    for (int o = 16; o; o >>= 1) v += __shfl_xor_sync(0xffffffffu, v, o);
    __shared__ int sp[SCAN_TB / 32];
    if (lane == 0) sp[warp] = v;
    __syncthreads();
    if (threadIdx.x < 32) {
        int s = sp[threadIdx.x];
        #pragma unroll
        for (int o = 16; o; o >>= 1) s += __shfl_xor_sync(0xffffffffu, s, o);
        if (threadIdx.x == 0) g_bsum[blockIdx.x] = s;
    }
}

// ---- scan phase C (scanB folded in): rowptr + cursors + scales + B0 ----
__global__ void k_scanC(int n) {
    GRID_DEP_SYNC();
    __shared__ int s_boff;
    __shared__ int sp[SCAN_TB / 32];

    // this block's global offset: sum of g_bsum[0 .. blockIdx.x)
    if (threadIdx.x < 32) {
        int a = 0;
        for (int j = threadIdx.x; j < blockIdx.x; j += 32) a += g_bsum[j];
        #pragma unroll
        for (int o = 16; o; o >>= 1) a += __shfl_xor_sync(0xffffffffu, a, o);
        if (threadIdx.x == 0) s_boff = a;
    }

    int i    = blockIdx.x * SCAN_TB + threadIdx.x;
    int lane = threadIdx.x & 31;
    int warp = threadIdx.x >> 5;
    int cnt = (i < n) ? g_cnt[i] : 0;
    int t = cnt;
    #pragma unroll
    for (int o = 1; o < 32; o <<= 1) {
        int u = __shfl_up_sync(0xffffffffu, t, o);
        if (lane >= o) t += u;
    }
    if (lane == 31) sp[warp] = t;
    __syncthreads();
    if (threadIdx.x < 32) {
        int w = sp[threadIdx.x];
        #pragma unroll
        for (int o = 1; o < 32; o <<= 1) {
            int u = __shfl_up_sync(0xffffffffu, w, o);
            if (threadIdx.x >= o) w += u;
        }
        sp[threadIdx.x] = w;
    }
    __syncthreads();
    int woff = (warp > 0) ? sp[warp - 1] : 0;
    if (i < n) {
        int excl = s_boff + woff + t - cnt;
        g_bstart[i] = excl;
        g_cur[i]    = excl;
        if (i == n - 1) g_bstart[n] = excl + cnt;
        float deg  = (float)(cnt + 1);     // +1 self-loop
        float dinv = __frcp_rn(deg);
        float dis  = rsqrtf(deg);
        g_dinv[i]   = dinv;
        g_dis[i]    = dis;
        g_buf[0][i] = make_float2(g_dot[i], dis);
    }
}

// ---- place: g_row[bump(col)] = row (4B random store + bump atomic) ----
__global__ void k_place(const int* __restrict__ row, const int* __restrict__ col, int E) {
    GRID_DEP_SYNC();
    int tid = blockIdx.x * blockDim.x + threadIdx.x;
    int nth = gridDim.x * blockDim.x;
    int E4  = E >> 2;
    for (int q = tid; q < E4; q += nth) {
        int4 r = reinterpret_cast<const int4*>(row)[q];
        int4 c = reinterpret_cast<const int4*>(col)[q];
        int p0 = atomicAdd(&g_cur[c.x], 1);
        int p1 = atomicAdd(&g_cur[c.y], 1);
        int p2 = atomicAdd(&g_cur[c.z], 1);
        int p3 = atomicAdd(&g_cur[c.w], 1);
        g_row[p0] = r.x;
        g_row[p1] = r.y;
        g_row[p2] = r.z;
        g_row[p3] = r.w;
    }
    if (tid == 0) {
        for (int e = E4 << 2; e < E; e++) {
            int p = atomicAdd(&g_cur[col[e]], 1);
            g_row[p] = row[e];
        }
    }
}

// ---- one hop, rowptr form: 2 threads per destination col, no atomics ----
// dst[c] = { sum_{r in in(c)} src[r].t*src[r].s + src[c].t*src[c].s,  next_scale }
template<int SRC>
__global__ void k_hop(int n) {
    GRID_DEP_SYNC();
    const float2* __restrict__ src = g_buf[SRC];
    float2*       __restrict__ dst = g_buf[SRC + 1];
    int tid  = blockIdx.x * blockDim.x + threadIdx.x;
    int c    = tid >> 1;
    int half = tid & 1;
    bool valid = c < n;
    int s = 0, e = 0;
    if (valid) { s = g_bstart[c]; e = g_bstart[c + 1]; }
    float acc = 0.0f;
    #pragma unroll 4
    for (int i = s + half; i < e; i += 2) {
        float2 a = __ldg(&src[g_row[i]]);
        acc += a.x * a.y;
    }
    acc += __shfl_xor_sync(0xffffffffu, acc, 1);   // pair lanes always converged here
    if (valid && half == 0) {
        float2 sl = src[c];                         // self-loop term
        float sc = (SRC == 2) ? g_dis[c] : g_dinv[c];
        dst[c] = make_float2(acc + sl.x * sl.y, sc);
    }
}

// ---- fused scatter-mean + output: block g owns graph g (batch sorted) ----
__global__ void k_out(const int* __restrict__ batch, const float* __restrict__ bias,
                      float* __restrict__ out, int n) {
    GRID_DEP_SYNC();
    __shared__ int s_lo, s_hi;
    __shared__ float s_part[8];
    int g = blockIdx.x;

    if (threadIdx.x < 2) {
        int target = g + threadIdx.x;
        int lo = 0, hi = n;
        while (lo < hi) {
            int mid = (lo + hi) >> 1;
            if (batch[mid] < target) lo = mid + 1; else hi = mid;
        }
        if (threadIdx.x == 0) s_lo = lo; else s_hi = lo;
    }
    __syncthreads();

    int lo = s_lo, hi = s_hi;
    float local = 0.0f;
    for (int i = lo + threadIdx.x; i < hi; i += blockDim.x) {
        float2 v = g_buf[3][i];                    // {t3, dis}
        local += v.x * v.y;
    }

    #pragma unroll
    for (int o = 16; o; o >>= 1) local += __shfl_xor_sync(0xffffffffu, local, o);
    int warp = threadIdx.x >> 5;
    if ((threadIdx.x & 31) == 0) s_part[warp] = local;
    __syncthreads();
    if (threadIdx.x == 0) {
        float sum = 0.0f;
        #pragma unroll
        for (int w = 0; w < 8; w++) sum += s_part[w];
        int c = hi - lo;
        out[g] = (c > 0) ? (sum / (float)c + bias[0]) : 0.0f;
    }
}

// ---------------------------------------------------------------------------
extern "C" void kernel_launch(void* const* d_in, const int* in_sizes, int n_in,
                              void* d_out, int out_size) {
    const float* x     = (const float*)d_in[0];
    const float* W     = (const float*)d_in[1];
    const float* b     = (const float*)d_in[2];
    const int*   ei    = (const int*)d_in[3];
    const int*   batch = (const int*)d_in[4];

    int F = in_sizes[1];
    int n = in_sizes[4];
    int E = in_sizes[3] / 2;
    int G = out_size;

    const int* row = ei;
    const int* col = ei + E;

    const int TB = 256;
    auto nbk = [](int v, int tb) { return (v + tb - 1) / tb; };

    void* p_cnt;
    cudaGetSymbolAddress(&p_cnt, g_cnt);
    cudaMemsetAsync(p_cnt, 0, (size_t)n * sizeof(int));

    cudaLaunchAttribute pdlAttr[1];
    pdlAttr[0].id = cudaLaunchAttributeProgrammaticStreamSerialization;
    pdlAttr[0].val.programmaticStreamSerializationAllowed = 1;

    int nGemv = NSM * 4;
    int nDeg  = NSM * 4;
    k_pre<<<nGemv + nDeg, TB>>>(x, W, col, n, F, E, nGemv);

    {
        cudaLaunchConfig_t cfg = {};
        cfg.attrs = pdlAttr;
        cfg.numAttrs = 1;

        int nA = nbk(n, SCAN_TB);        // <= 128 for MAXN
        cfg.blockDim = dim3(SCAN_TB, 1, 1);
        cfg.gridDim  = dim3(nA, 1, 1);
        cudaLaunchKernelEx(&cfg, k_scanA, n);
        cudaLaunchKernelEx(&cfg, k_scanC, n);

        cfg.blockDim = dim3(TB, 1, 1);
        cfg.gridDim  = dim3(NSM * 8, 1, 1);
        cudaLaunchKernelEx(&cfg, k_place, row, col, E);

        cfg.gridDim = dim3(nbk(2 * n, TB), 1, 1);   // 2 threads per col
        cudaLaunchKernelEx(&cfg, k_hop<0>, n);
        cudaLaunchKernelEx(&cfg, k_hop<1>, n);
        cudaLaunchKernelEx(&cfg, k_hop<2>, n);

        cfg.gridDim = dim3(G, 1, 1);
        cudaLaunchKernelEx(&cfg, k_out, batch, b, (float*)d_out, n);
    }
}